// round 4
// baseline (speedup 1.0000x reference)
#include <cuda_runtime.h>
#include <cuda_bf16.h>

#define IMAGE 224
#define PAD   30
#define CROP  (IMAGE - 2 * PAD)   // 164
#define NB    16
#define NT    16
#define W4    (IMAGE / 4)         // 56

__global__ __launch_bounds__(256) void prompt_add_kernel(
    const float* __restrict__ x,
    const float* __restrict__ pu1,  const float* __restrict__ pu10,
    const float* __restrict__ pd1,  const float* __restrict__ pd10,
    const float* __restrict__ pl1,  const float* __restrict__ pl10,
    const float* __restrict__ pr1,  const float* __restrict__ pr10,
    const int*   __restrict__ cam_idx,
    const int*   __restrict__ off_right,
    const int*   __restrict__ off_down,
    float* __restrict__ out)
{
    int idx = blockIdx.x * blockDim.x + threadIdx.x;
    // idx in [0, NB*3*IMAGE*W4) — exact multiple of 256, no bounds check needed,
    // but keep one for safety against grid rounding.
    const int total = NB * 3 * IMAGE * W4;
    if (idx >= total) return;

    int w4 = idx % W4;
    int h  = (idx / W4) % IMAGE;
    int c  = (idx / (W4 * IMAGE)) % 3;
    int b  =  idx / (W4 * IMAGE * 3);

    const int ci  = cam_idx[b];
    const int orr = off_right[b];   // in [1, 30]
    const int od  = off_down[b];    // in [1, 30]

    const int off_l = 2 * PAD - orr;     // [30, 59]
    const int off_u = 2 * PAD - od;      // [30, 59]
    const int n10_l = off_l / 10;
    const int n10_u = off_u / 10;
    const int n1_r  = orr % 10;
    const int n1_d  = od % 10;

    int r = h - off_u;
    r = r < 0 ? 0 : (r > CROP - 1 ? CROP - 1 : r);
    const int hd = h - (IMAGE - od);

    // per-(ci, c) pad table bases
    const float* PU1  = pu1  + (ci * 3 + c) * IMAGE;       // [224]
    const float* PU10 = pu10 + (ci * 3 + c) * 10 * IMAGE;  // [10,224]
    const float* PD1  = pd1  + (ci * 3 + c) * IMAGE;
    const float* PD10 = pd10 + (ci * 3 + c) * 10 * IMAGE;
    const float* PL1  = pl1  + (ci * 3 + c) * CROP;        // [164]
    const float* PL10 = pl10 + (ci * 3 + c) * CROP * 10;   // [164,10]
    const float* PR1  = pr1  + (ci * 3 + c) * CROP;
    const float* PR10 = pr10 + (ci * 3 + c) * CROP * 10;

    // ------- build the 4 prompt scalars for this w-quad -------
    float p[4];
    #pragma unroll
    for (int k = 0; k < 4; k++) {
        const int w = w4 * 4 + k;
        float v;
        if (h < off_u) {
            // top border
            v = (h < n10_u * 10) ? __ldg(&PU10[(h % 10) * IMAGE + w])
                                 : __ldg(&PU1[w]);
        } else if (h >= IMAGE - od) {
            // bottom border
            if (hd < n1_d) {
                v = __ldg(&PD1[w]);
            } else {
                const int di = (hd - n1_d) % 10;   // hd - n1_d >= 0 here
                v = __ldg(&PD10[di * IMAGE + w]);
            }
        } else {
            // middle rows: left border / right border / interior zero
            if (w < off_l) {
                v = (w < n10_l * 10) ? __ldg(&PL10[r * 10 + (w % 10)])
                                     : __ldg(&PL1[r]);
            } else if (w >= IMAGE - orr) {
                const int wd = w - (IMAGE - orr);  // wd >= 0 here
                if (wd < n1_r) {
                    v = __ldg(&PR1[r]);
                } else {
                    const int ri = (wd - n1_r) % 10;
                    v = __ldg(&PR10[r * 10 + ri]);
                }
            } else {
                v = 0.0f;
            }
        }
        p[k] = v;
    }

    // ------- stream x across T with float4, add prompt, store -------
    const size_t plane = (size_t)IMAGE * IMAGE;                 // 50176
    const size_t base  = ((size_t)(b * 3 + c) * NT) * plane
                       + (size_t)h * IMAGE + (size_t)w4 * 4;

    #pragma unroll
    for (int t = 0; t < NT; t++) {
        const size_t off = base + (size_t)t * plane;
        float4 xv = *reinterpret_cast<const float4*>(x + off);
        xv.x += p[0];
        xv.y += p[1];
        xv.z += p[2];
        xv.w += p[3];
        *reinterpret_cast<float4*>(out + off) = xv;
    }
}

extern "C" void kernel_launch(void* const* d_in, const int* in_sizes, int n_in,
                              void* d_out, int out_size) {
    const float* x    = (const float*)d_in[0];
    const float* pu1  = (const float*)d_in[1];
    const float* pu10 = (const float*)d_in[2];
    const float* pd1  = (const float*)d_in[3];
    const float* pd10 = (const float*)d_in[4];
    const float* pl1  = (const float*)d_in[5];
    const float* pl10 = (const float*)d_in[6];
    const float* pr1  = (const float*)d_in[7];
    const float* pr10 = (const float*)d_in[8];
    const int* cam_idx   = (const int*)d_in[9];
    const int* off_right = (const int*)d_in[10];
    const int* off_down  = (const int*)d_in[11];
    float* out = (float*)d_out;

    const int total   = NB * 3 * IMAGE * W4;   // 602112
    const int threads = 256;
    const int blocks  = (total + threads - 1) / threads;  // 2352

    prompt_add_kernel<<<blocks, threads>>>(
        x, pu1, pu10, pd1, pd10, pl1, pl10, pr1, pr10,
        cam_idx, off_right, off_down, out);
}